// round 9
// baseline (speedup 1.0000x reference)
#include <cuda_runtime.h>
#include <math_constants.h>
#include <cstdint>

#define HD     1024
#define NHEADS 16
#define DHEAD  64
#define SEQ    2048
#define NB     2
#define ROWS   (NB * SEQ)   // 4096

// Scratch (allocation-free rule: __device__ globals)
__device__ float g_q[ROWS * HD];     // tf32-rounded by qkv epilogue
__device__ float g_k[ROWS * HD];     // tf32-rounded by qkv epilogue
__device__ float g_v[ROWS * HD];     // tf32-rounded by qkv epilogue
__device__ float g_ctx[ROWS * HD];   // raw fp32 (out_gemm CVTs in-loop)

// ---------------------------------------------------------------------------
// Helpers
// ---------------------------------------------------------------------------
__device__ __forceinline__ uint32_t cvt_tf32(float x) {
    uint32_t u;
    asm("cvt.rna.tf32.f32 %0, %1;" : "=r"(u) : "f"(x));
    return u;
}
__device__ __forceinline__ float rnd_tf32(float x) {
    return __uint_as_float(cvt_tf32(x));
}
__device__ __forceinline__ void cp16(void* dst, const void* src) {
    uint32_t d = (uint32_t)__cvta_generic_to_shared(dst);
    asm volatile("cp.async.cg.shared.global [%0], [%1], 16;" :: "r"(d), "l"(src));
}
#define CP_COMMIT()  asm volatile("cp.async.commit_group;" ::: "memory")
#define CP_WAIT(n)   asm volatile("cp.async.wait_group %0;" :: "n"(n) : "memory")

__device__ __forceinline__ void mma_tf32(float* d, const uint32_t* a, const uint32_t* b) {
    asm volatile("mma.sync.aligned.m16n8k8.row.col.f32.tf32.tf32.f32 "
                 "{%0,%1,%2,%3}, {%4,%5,%6,%7}, {%8,%9}, {%0,%1,%2,%3};"
                 : "+f"(d[0]), "+f"(d[1]), "+f"(d[2]), "+f"(d[3])
                 : "r"(a[0]), "r"(a[1]), "r"(a[2]), "r"(a[3]),
                   "r"(b[0]), "r"(b[1]));
}

// ---------------------------------------------------------------------------
// tf32 tensor-core GEMM: C[M,N] = A[M,K] @ B[K,N], all row-major fp32.
// CTA tile 128x128, 8 warps (4m x 2n), warp tile 32x64, K staged by 16,
// cp.async double-buffered. Fragments rounded to tf32 with RNA in registers
// (the CVTs double as independent alu work between LDS and MMA — R8 showed
// removing them REGRESSES; keep them).
// ROUND_OUT: round the stored C to tf32 (for q/k/v, consumed by flash mma).
// ---------------------------------------------------------------------------
struct GemmSmem {
    float As[2][128][20];
    float Bs[2][16][132];
};

__device__ __forceinline__ void gemm_stage_load(const float* __restrict__ A,
                                                const float* __restrict__ B,
                                                GemmSmem* sm, int buf,
                                                int bm, int bn, int k0, int tid)
{
#pragma unroll
    for (int i = 0; i < 2; i++) {
        int c = tid + i * 256;
        int ar = c >> 2, ac = c & 3;
        cp16(&sm->As[buf][ar][ac * 4], &A[(size_t)(bm + ar) * HD + k0 + ac * 4]);
        int br = c >> 5, bc = c & 31;
        cp16(&sm->Bs[buf][br][bc * 4], &B[(size_t)(k0 + br) * HD + bn + bc * 4]);
    }
}

template <bool ROUND_OUT>
__device__ __forceinline__ void gemm_tf32_body(const float* __restrict__ A,
                                               const float* __restrict__ B,
                                               float* __restrict__ C)
{
    __shared__ GemmSmem sm;

    const int tid  = threadIdx.x;
    const int lane = tid & 31;
    const int warp = tid >> 5;
    const int wm   = warp >> 1;
    const int wn   = warp & 1;
    const int m0   = wm * 32;
    const int n0   = wn * 64;
    const int gr   = lane >> 2;
    const int tg   = lane & 3;
    const int bm   = blockIdx.y << 7;
    const int bn   = blockIdx.x << 7;

    float acc[2][8][4];
#pragma unroll
    for (int mi = 0; mi < 2; mi++)
#pragma unroll
        for (int ni = 0; ni < 8; ni++)
#pragma unroll
            for (int j = 0; j < 4; j++) acc[mi][ni][j] = 0.0f;

    gemm_stage_load(A, B, &sm, 0, bm, bn, 0, tid);
    CP_COMMIT();

    for (int s = 0; s < 64; s++) {
        const int buf = s & 1;
        if (s < 63) {
            gemm_stage_load(A, B, &sm, buf ^ 1, bm, bn, (s + 1) << 4, tid);
            CP_COMMIT();
            CP_WAIT(1);
        } else {
            CP_WAIT(0);
        }
        __syncthreads();

#pragma unroll
        for (int kk = 0; kk < 16; kk += 8) {
            uint32_t a[2][4], b[8][2];
#pragma unroll
            for (int mi = 0; mi < 2; mi++) {
                int r = m0 + mi * 16 + gr;
                a[mi][0] = cvt_tf32(sm.As[buf][r][kk + tg]);
                a[mi][1] = cvt_tf32(sm.As[buf][r + 8][kk + tg]);
                a[mi][2] = cvt_tf32(sm.As[buf][r][kk + tg + 4]);
                a[mi][3] = cvt_tf32(sm.As[buf][r + 8][kk + tg + 4]);
            }
#pragma unroll
            for (int ni = 0; ni < 8; ni++) {
                int cc = n0 + ni * 8 + gr;
                b[ni][0] = cvt_tf32(sm.Bs[buf][kk + tg][cc]);
                b[ni][1] = cvt_tf32(sm.Bs[buf][kk + tg + 4][cc]);
            }
#pragma unroll
            for (int mi = 0; mi < 2; mi++)
#pragma unroll
                for (int ni = 0; ni < 8; ni++)
                    mma_tf32(acc[mi][ni], a[mi], b[ni]);
        }
        __syncthreads();
    }

#pragma unroll
    for (int mi = 0; mi < 2; mi++) {
#pragma unroll
        for (int ni = 0; ni < 8; ni++) {
            int r  = bm + m0 + mi * 16 + gr;
            int cc = bn + n0 + ni * 8 + 2 * tg;
            float2 v0, v1;
            if (ROUND_OUT) {
                v0 = make_float2(rnd_tf32(acc[mi][ni][0]), rnd_tf32(acc[mi][ni][1]));
                v1 = make_float2(rnd_tf32(acc[mi][ni][2]), rnd_tf32(acc[mi][ni][3]));
            } else {
                v0 = make_float2(acc[mi][ni][0], acc[mi][ni][1]);
                v1 = make_float2(acc[mi][ni][2], acc[mi][ni][3]);
            }
            *reinterpret_cast<float2*>(&C[(size_t)r * HD + cc]) = v0;
            *reinterpret_cast<float2*>(&C[(size_t)(r + 8) * HD + cc]) = v1;
        }
    }
}

__global__ __launch_bounds__(256, 2)
void qkv_gemm_kernel(const float* __restrict__ X,
                     const float* __restrict__ Wq,
                     const float* __restrict__ Wk,
                     const float* __restrict__ Wv)
{
    const int z = blockIdx.z;
    const float* W = (z == 0) ? Wq : (z == 1) ? Wk : Wv;
    float* O = (z == 0) ? g_q : (z == 1) ? g_k : g_v;
    gemm_tf32_body<true>(X, W, O);    // rounded: consumed by flash mma
}

__global__ __launch_bounds__(256, 2)
void out_gemm_kernel(const float* __restrict__ Wo, float* __restrict__ Out)
{
    gemm_tf32_body<false>(g_ctx, Wo, Out);   // final output: NOT rounded
}

// ---------------------------------------------------------------------------
// Tensor-core flash attention (tf32 mma.sync). BQ=64, BKV=64, d=64.
// 4 warps; warp w owns query rows [w*16, w*16+16). Full softmax row in-warp.
// q/k/v are pre-rounded by the qkv epilogue, so staging is pure cp.async
// (no CVT, no LDG->reg->STS round trip). Same mma operand bits as R5.
// ---------------------------------------------------------------------------
struct FlashSmem {
    float QP[64][68];
    float K[64][68];
    float V[64][72];
    float amk[64];
};
#define FLASH_SMEM ((int)sizeof(FlashSmem))

__global__ __launch_bounds__(128)
void flash_tc_kernel(const float* __restrict__ am)
{
    extern __shared__ char smem_raw[];
    FlashSmem& sm = *reinterpret_cast<FlashSmem*>(smem_raw);

    const int tid  = threadIdx.x;
    const int lane = tid & 31;
    const int warp = tid >> 5;
    const int gr   = lane >> 2;
    const int tg   = lane & 3;
    const int m0   = warp * 16;

    const int qb = blockIdx.x;
    const int h  = blockIdx.y;
    const int b  = blockIdx.z;
    const int qbase = qb * 64;
    const size_t gbase = (size_t)b * SEQ * HD + h * DHEAD;

    // Stage Q via cp.async (already tf32-rounded in gmem)
#pragma unroll
    for (int it = 0; it < 8; ++it) {
        int id = tid + it * 128;
        int r = id >> 4, c4 = id & 15;
        cp16(&sm.QP[r][c4 * 4], &g_q[gbase + (size_t)(qbase + r) * HD + c4 * 4]);
    }
    CP_COMMIT();
    const float amq0 = am[b * SEQ + qbase + m0 + gr];
    const float amq1 = am[b * SEQ + qbase + m0 + 8 + gr];
    CP_WAIT(0);
    __syncthreads();

    // Preload Q fragments (warp-private rows)
    uint32_t aQ[8][4];
#pragma unroll
    for (int kt = 0; kt < 8; ++kt) {
        aQ[kt][0] = __float_as_uint(sm.QP[m0 + gr][kt * 8 + tg]);
        aQ[kt][1] = __float_as_uint(sm.QP[m0 + gr + 8][kt * 8 + tg]);
        aQ[kt][2] = __float_as_uint(sm.QP[m0 + gr][kt * 8 + tg + 4]);
        aQ[kt][3] = __float_as_uint(sm.QP[m0 + gr + 8][kt * 8 + tg + 4]);
    }

    float m0_i = -CUDART_INF_F, m1_i = -CUDART_INF_F;
    float l0 = 0.0f, l1 = 0.0f;
    float o[8][4];
#pragma unroll
    for (int nt = 0; nt < 8; ++nt)
#pragma unroll
        for (int j = 0; j < 4; ++j) o[nt][j] = 0.0f;

    const float MASKC = -3.402823466e38f;
    const int row0 = qbase + m0 + gr;
    const int row1 = row0 + 8;

    for (int kb = 0; kb <= qb; ++kb) {
        const int kvbase = kb * 64;
        __syncthreads();
        // Stage K, V via cp.async (pre-rounded in gmem; LSU-pipelined)
#pragma unroll
        for (int it = 0; it < 8; ++it) {
            int id = tid + it * 128;
            int r = id >> 4, c4 = id & 15;
            cp16(&sm.K[r][c4 * 4], &g_k[gbase + (size_t)(kvbase + r) * HD + c4 * 4]);
            cp16(&sm.V[r][c4 * 4], &g_v[gbase + (size_t)(kvbase + r) * HD + c4 * 4]);
        }
        CP_COMMIT();
        if (tid < 64) sm.amk[tid] = am[b * SEQ + kvbase + tid];
        CP_WAIT(0);
        __syncthreads();

        // S = Q K^T  (warp computes m16 x n64)
        float s[8][4];
#pragma unroll
        for (int nt = 0; nt < 8; ++nt) {
#pragma unroll
            for (int j = 0; j < 4; ++j) s[nt][j] = 0.0f;
#pragma unroll
            for (int kt = 0; kt < 8; ++kt) {
                uint32_t bk[2];
                bk[0] = __float_as_uint(sm.K[nt * 8 + gr][kt * 8 + tg]);
                bk[1] = __float_as_uint(sm.K[nt * 8 + gr][kt * 8 + tg + 4]);
                mma_tf32(s[nt], aQ[kt], bk);
            }
        }

        // Mask (faithful) + row max
        float mx0 = -CUDART_INF_F, mx1 = -CUDART_INF_F;
#pragma unroll
        for (int nt = 0; nt < 8; ++nt) {
            const int col = kvbase + nt * 8 + 2 * tg;
            const float ak0 = sm.amk[nt * 8 + 2 * tg];
            const float ak1 = sm.amk[nt * 8 + 2 * tg + 1];
            float mv;
            mv = fmaxf((col     > row0) ? 1.0f : 0.0f, 1.0f - amq0 * ak0);
            s[nt][0] = (s[nt][0] + MASKC * mv) * 0.03125f;
            mv = fmaxf((col + 1 > row0) ? 1.0f : 0.0f, 1.0f - amq0 * ak1);
            s[nt][1] = (s[nt][1] + MASKC * mv) * 0.03125f;
            mv = fmaxf((col     > row1) ? 1.0f : 0.0f, 1.0f - amq1 * ak0);
            s[nt][2] = (s[nt][2] + MASKC * mv) * 0.03125f;
            mv = fmaxf((col + 1 > row1) ? 1.0f : 0.0f, 1.0f - amq1 * ak1);
            s[nt][3] = (s[nt][3] + MASKC * mv) * 0.03125f;
            mx0 = fmaxf(mx0, fmaxf(s[nt][0], s[nt][1]));
            mx1 = fmaxf(mx1, fmaxf(s[nt][2], s[nt][3]));
        }
        mx0 = fmaxf(mx0, __shfl_xor_sync(0xffffffffu, mx0, 1));
        mx0 = fmaxf(mx0, __shfl_xor_sync(0xffffffffu, mx0, 2));
        mx1 = fmaxf(mx1, __shfl_xor_sync(0xffffffffu, mx1, 1));
        mx1 = fmaxf(mx1, __shfl_xor_sync(0xffffffffu, mx1, 2));

        const float mn0 = fmaxf(m0_i, mx0);
        const float mn1 = fmaxf(m1_i, mx1);
        const float f0 = __expf(m0_i - mn0);
        const float f1 = __expf(m1_i - mn1);

        float rs0 = 0.0f, rs1 = 0.0f;
#pragma unroll
        for (int nt = 0; nt < 8; ++nt) {
            float p00 = __expf(s[nt][0] - mn0);
            float p01 = __expf(s[nt][1] - mn0);
            float p10 = __expf(s[nt][2] - mn1);
            float p11 = __expf(s[nt][3] - mn1);
            rs0 += p00 + p01;
            rs1 += p10 + p11;
            float2 w0 = make_float2(rnd_tf32(p00), rnd_tf32(p01));
            float2 w1 = make_float2(rnd_tf32(p10), rnd_tf32(p11));
            *reinterpret_cast<float2*>(&sm.QP[m0 + gr][nt * 8 + 2 * tg]) = w0;
            *reinterpret_cast<float2*>(&sm.QP[m0 + gr + 8][nt * 8 + 2 * tg]) = w1;
        }
        rs0 += __shfl_xor_sync(0xffffffffu, rs0, 1);
        rs0 += __shfl_xor_sync(0xffffffffu, rs0, 2);
        rs1 += __shfl_xor_sync(0xffffffffu, rs1, 1);
        rs1 += __shfl_xor_sync(0xffffffffu, rs1, 2);

        l0 = l0 * f0 + rs0;
        l1 = l1 * f1 + rs1;
        m0_i = mn0;
        m1_i = mn1;
#pragma unroll
        for (int nt = 0; nt < 8; ++nt) {
            o[nt][0] *= f0;  o[nt][1] *= f0;
            o[nt][2] *= f1;  o[nt][3] *= f1;
        }
        __syncwarp();

        // O += P V
#pragma unroll
        for (int kt = 0; kt < 8; ++kt) {
            uint32_t aP[4];
            aP[0] = __float_as_uint(sm.QP[m0 + gr][kt * 8 + tg]);
            aP[1] = __float_as_uint(sm.QP[m0 + gr + 8][kt * 8 + tg]);
            aP[2] = __float_as_uint(sm.QP[m0 + gr][kt * 8 + tg + 4]);
            aP[3] = __float_as_uint(sm.QP[m0 + gr + 8][kt * 8 + tg + 4]);
#pragma unroll
            for (int nt = 0; nt < 8; ++nt) {
                uint32_t bv[2];
                bv[0] = __float_as_uint(sm.V[kt * 8 + tg][nt * 8 + gr]);
                bv[1] = __float_as_uint(sm.V[kt * 8 + tg + 4][nt * 8 + gr]);
                mma_tf32(o[nt], aP, bv);
            }
        }
        __syncwarp();
    }

    // Epilogue: normalize + write ctx (raw fp32; out_gemm CVTs in-loop)
    const float inv0 = 1.0f / l0;
    const float inv1 = 1.0f / l1;
#pragma unroll
    for (int nt = 0; nt < 8; ++nt) {
        const int cc = nt * 8 + 2 * tg;
        float2 v0 = make_float2(o[nt][0] * inv0, o[nt][1] * inv0);
        float2 v1 = make_float2(o[nt][2] * inv1, o[nt][3] * inv1);
        *reinterpret_cast<float2*>(&g_ctx[gbase + (size_t)row0 * HD + cc]) = v0;
        *reinterpret_cast<float2*>(&g_ctx[gbase + (size_t)row1 * HD + cc]) = v1;
    }
}

// ---------------------------------------------------------------------------
extern "C" void kernel_launch(void* const* d_in, const int* in_sizes, int n_in,
                              void* d_out, int out_size)
{
    const float* input = (const float*)d_in[0];
    const float* amask = (const float*)d_in[1];
    const float* wq    = (const float*)d_in[2];
    const float* wk    = (const float*)d_in[3];
    const float* wv    = (const float*)d_in[4];
    const float* wo    = (const float*)d_in[5];
    float* out = (float*)d_out;

    cudaFuncSetAttribute(flash_tc_kernel,
                         cudaFuncAttributeMaxDynamicSharedMemorySize, FLASH_SMEM);

    dim3 gq(HD / 128, ROWS / 128, 3);     // (8, 32, 3)
    qkv_gemm_kernel<<<gq, 256>>>(input, wq, wk, wv);

    dim3 gf(SEQ / 64, NHEADS, NB);        // (32, 16, 2)
    flash_tc_kernel<<<gf, 128, FLASH_SMEM>>>(amask);

    dim3 go(HD / 128, ROWS / 128);        // (8, 32)
    out_gemm_kernel<<<go, 256>>>(wo, out);
}

// round 12
// speedup vs baseline: 2.6590x; 2.6590x over previous
#include <cuda_runtime.h>
#include <cuda_fp16.h>
#include <math_constants.h>
#include <cstdint>

#define HD     1024
#define NHEADS 16
#define DHEAD  64
#define SEQ    2048
#define NB     2
#define ROWS   (NB * SEQ)   // 4096

// Scratch (allocation-free rule: __device__ globals)
__device__ __half g_xh[ROWS * HD];        // half(X)
__device__ __half g_wth[4][HD * HD];      // half(W^T): [z][n*HD + k]
__device__ __half g_qh[ROWS * HD];
__device__ __half g_kh[ROWS * HD];
__device__ __half g_vh[ROWS * HD];
__device__ __half g_ch[ROWS * HD];        // ctx half

// ---------------------------------------------------------------------------
// Helpers
// ---------------------------------------------------------------------------
__device__ __forceinline__ void cp16(void* dst, const void* src) {
    uint32_t d = (uint32_t)__cvta_generic_to_shared(dst);
    asm volatile("cp.async.cg.shared.global [%0], [%1], 16;" :: "r"(d), "l"(src));
}
#define CP_COMMIT()  asm volatile("cp.async.commit_group;" ::: "memory")
#define CP_WAIT(n)   asm volatile("cp.async.wait_group %0;" :: "n"(n) : "memory")

__device__ __forceinline__ void mma_f16(float* d, const uint32_t* a, const uint32_t* b) {
    asm volatile("mma.sync.aligned.m16n8k16.row.col.f32.f16.f16.f32 "
                 "{%0,%1,%2,%3}, {%4,%5,%6,%7}, {%8,%9}, {%0,%1,%2,%3};"
                 : "+f"(d[0]), "+f"(d[1]), "+f"(d[2]), "+f"(d[3])
                 : "r"(a[0]), "r"(a[1]), "r"(a[2]), "r"(a[3]),
                   "r"(b[0]), "r"(b[1]));
}
__device__ __forceinline__ void ldmatrix_x4_trans(uint32_t& r0, uint32_t& r1,
                                                  uint32_t& r2, uint32_t& r3,
                                                  uint32_t addr) {
    asm volatile("ldmatrix.sync.aligned.m8n8.x4.trans.shared.b16 {%0,%1,%2,%3}, [%4];"
                 : "=r"(r0), "=r"(r1), "=r"(r2), "=r"(r3) : "r"(addr));
}
__device__ __forceinline__ uint32_t ld_u32s(const void* p) {
    return *reinterpret_cast<const uint32_t*>(p);
}

// ---------------------------------------------------------------------------
// Prepass 1: X -> half
// ---------------------------------------------------------------------------
__global__ void xhalf_kernel(const float* __restrict__ X)
{
    int i = blockIdx.x * blockDim.x + threadIdx.x;   // over ROWS*HD/4
    float4 v = reinterpret_cast<const float4*>(X)[i];
    __half2 h0 = __floats2half2_rn(v.x, v.y);
    __half2 h1 = __floats2half2_rn(v.z, v.w);
    uint2 u;
    u.x = *reinterpret_cast<uint32_t*>(&h0);
    u.y = *reinterpret_cast<uint32_t*>(&h1);
    reinterpret_cast<uint2*>(g_xh)[i] = u;
}

// Prepass 2: W_z -> half(W^T). Block 32x8, tile 32x32.
__global__ void wtrans_kernel(const float* __restrict__ wq,
                              const float* __restrict__ wk,
                              const float* __restrict__ wv,
                              const float* __restrict__ wo)
{
    __shared__ float t[32][33];
    const int z = blockIdx.z;
    const float* W = (z == 0) ? wq : (z == 1) ? wk : (z == 2) ? wv : wo;
    __half* O = g_wth[z];
    const int bx = blockIdx.x * 32;   // n tile
    const int by = blockIdx.y * 32;   // k tile
    const int tx = threadIdx.x, ty = threadIdx.y;
#pragma unroll
    for (int i = 0; i < 4; i++)
        t[ty + i * 8][tx] = W[(size_t)(by + ty + i * 8) * HD + bx + tx];
    __syncthreads();
#pragma unroll
    for (int i = 0; i < 4; i++)
        O[(size_t)(bx + ty + i * 8) * HD + by + tx] = __float2half_rn(t[tx][ty + i * 8]);
}

// ---------------------------------------------------------------------------
// fp16 tensor-core GEMM: C[M,N] = A[M,K] @ B[K,N]; A half row-major,
// BT = half(B^T) [N,K]. CTA 128x128, 8 warps (4m x 2n), warp 32x64,
// K chunk 32, cp.async double-buffered. Pads (40 halves = 20 words) give
// conflict-free half2 fragment reads.
// ---------------------------------------------------------------------------
struct GemmSmemH {
    __half A[2][128][40];
    __half B[2][128][40];
};

__device__ __forceinline__ void gemm_stage_h(const __half* __restrict__ A,
                                             const __half* __restrict__ BT,
                                             GemmSmemH* sm, int buf,
                                             int bm, int bn, int k0, int tid)
{
#pragma unroll
    for (int i = 0; i < 2; i++) {
        int id = tid + i * 256;                 // 0..511
        int r = id >> 2, c = id & 3;            // 128 rows x 4 x 16B
        cp16(&sm->A[buf][r][c * 8], &A[(size_t)(bm + r) * HD + k0 + c * 8]);
        cp16(&sm->B[buf][r][c * 8], &BT[(size_t)(bn + r) * HD + k0 + c * 8]);
    }
}

template <bool HALF_OUT>
__device__ __forceinline__ void gemm_f16_body(const __half* __restrict__ A,
                                              const __half* __restrict__ BT,
                                              void* __restrict__ Cv)
{
    __shared__ GemmSmemH sm;

    const int tid  = threadIdx.x;
    const int lane = tid & 31;
    const int warp = tid >> 5;
    const int wm   = warp >> 1;
    const int wn   = warp & 1;
    const int m0   = wm * 32;
    const int n0   = wn * 64;
    const int gr   = lane >> 2;
    const int tg   = lane & 3;
    const int bm   = blockIdx.y << 7;
    const int bn   = blockIdx.x << 7;

    float acc[2][8][4];
#pragma unroll
    for (int mi = 0; mi < 2; mi++)
#pragma unroll
        for (int ni = 0; ni < 8; ni++)
#pragma unroll
            for (int j = 0; j < 4; j++) acc[mi][ni][j] = 0.0f;

    gemm_stage_h(A, BT, &sm, 0, bm, bn, 0, tid);
    CP_COMMIT();

    for (int s = 0; s < 32; s++) {
        const int buf = s & 1;
        if (s < 31) {
            gemm_stage_h(A, BT, &sm, buf ^ 1, bm, bn, (s + 1) << 5, tid);
            CP_COMMIT();
            CP_WAIT(1);
        } else {
            CP_WAIT(0);
        }
        __syncthreads();

#pragma unroll
        for (int kk = 0; kk < 32; kk += 16) {
            uint32_t a[2][4], b[8][2];
#pragma unroll
            for (int mi = 0; mi < 2; mi++) {
                int r = m0 + mi * 16 + gr;
                a[mi][0] = ld_u32s(&sm.A[buf][r][kk + 2 * tg]);
                a[mi][1] = ld_u32s(&sm.A[buf][r + 8][kk + 2 * tg]);
                a[mi][2] = ld_u32s(&sm.A[buf][r][kk + 2 * tg + 8]);
                a[mi][3] = ld_u32s(&sm.A[buf][r + 8][kk + 2 * tg + 8]);
            }
#pragma unroll
            for (int ni = 0; ni < 8; ni++) {
                int n = n0 + ni * 8 + gr;
                b[ni][0] = ld_u32s(&sm.B[buf][n][kk + 2 * tg]);
                b[ni][1] = ld_u32s(&sm.B[buf][n][kk + 2 * tg + 8]);
            }
#pragma unroll
            for (int mi = 0; mi < 2; mi++)
#pragma unroll
                for (int ni = 0; ni < 8; ni++)
                    mma_f16(acc[mi][ni], a[mi], b[ni]);
        }
        __syncthreads();
    }

#pragma unroll
    for (int mi = 0; mi < 2; mi++) {
#pragma unroll
        for (int ni = 0; ni < 8; ni++) {
            int r  = bm + m0 + mi * 16 + gr;
            int cc = bn + n0 + ni * 8 + 2 * tg;
            if (HALF_OUT) {
                __half* C = reinterpret_cast<__half*>(Cv);
                *reinterpret_cast<__half2*>(&C[(size_t)r * HD + cc]) =
                    __floats2half2_rn(acc[mi][ni][0], acc[mi][ni][1]);
                *reinterpret_cast<__half2*>(&C[(size_t)(r + 8) * HD + cc]) =
                    __floats2half2_rn(acc[mi][ni][2], acc[mi][ni][3]);
            } else {
                float* C = reinterpret_cast<float*>(Cv);
                *reinterpret_cast<float2*>(&C[(size_t)r * HD + cc]) =
                    make_float2(acc[mi][ni][0], acc[mi][ni][1]);
                *reinterpret_cast<float2*>(&C[(size_t)(r + 8) * HD + cc]) =
                    make_float2(acc[mi][ni][2], acc[mi][ni][3]);
            }
        }
    }
}

__global__ __launch_bounds__(256, 2)
void qkv_gemm_kernel()
{
    const int z = blockIdx.z;
    __half* O = (z == 0) ? g_qh : (z == 1) ? g_kh : g_vh;
    gemm_f16_body<true>(g_xh, g_wth[z], O);
}

__global__ __launch_bounds__(256, 2)
void out_gemm_kernel(float* __restrict__ Out)
{
    gemm_f16_body<false>(g_ch, g_wth[3], Out);
}

// ---------------------------------------------------------------------------
// fp16 tensor-core flash attention. BQ=64, BKV=64, d=64. 4 warps; warp w owns
// query rows [w*16, w*16+16); full softmax row in-warp. QP buffer holds Q then
// P (warp-private rows). V B-fragments via ldmatrix.x4.trans.
// Pads: 72 halves (36 words) -> conflict-free frags and ldmatrix rows.
// ---------------------------------------------------------------------------
struct FlashSmemH {
    __half QP[64][72];
    __half K[64][72];
    __half V[64][72];
    float amk[64];
};

__global__ __launch_bounds__(128)
void flash_tc_kernel(const float* __restrict__ am)
{
    __shared__ FlashSmemH sm;

    const int tid  = threadIdx.x;
    const int lane = tid & 31;
    const int warp = tid >> 5;
    const int gr   = lane >> 2;
    const int tg   = lane & 3;
    const int m0   = warp * 16;

    const int qb = blockIdx.x;
    const int h  = blockIdx.y;
    const int b  = blockIdx.z;
    const int qbase = qb * 64;
    const size_t gbase = (size_t)b * SEQ * HD + h * DHEAD;

    // Stage Q via cp.async (half, 8x16B per row)
#pragma unroll
    for (int it = 0; it < 4; ++it) {
        int id = tid + it * 128;
        int r = id >> 3, c = id & 7;
        cp16(&sm.QP[r][c * 8], &g_qh[gbase + (size_t)(qbase + r) * HD + c * 8]);
    }
    CP_COMMIT();
    const float amq0 = am[b * SEQ + qbase + m0 + gr];
    const float amq1 = am[b * SEQ + qbase + m0 + 8 + gr];
    CP_WAIT(0);
    __syncthreads();

    // Preload Q fragments (warp-private rows), 4 k-steps of 16
    uint32_t aQ[4][4];
#pragma unroll
    for (int kt = 0; kt < 4; ++kt) {
        aQ[kt][0] = ld_u32s(&sm.QP[m0 + gr][kt * 16 + 2 * tg]);
        aQ[kt][1] = ld_u32s(&sm.QP[m0 + gr + 8][kt * 16 + 2 * tg]);
        aQ[kt][2] = ld_u32s(&sm.QP[m0 + gr][kt * 16 + 2 * tg + 8]);
        aQ[kt][3] = ld_u32s(&sm.QP[m0 + gr + 8][kt * 16 + 2 * tg + 8]);
    }

    const uint32_t vbase = (uint32_t)__cvta_generic_to_shared(&sm.V[0][0]);
    const uint32_t vlrow = lane & 15;            // ldmatrix row within k16
    const uint32_t vlcol = (lane >> 4) * 8;      // n offset for lane group

    float m0_i = -CUDART_INF_F, m1_i = -CUDART_INF_F;
    float l0 = 0.0f, l1 = 0.0f;
    float o[8][4];
#pragma unroll
    for (int nt = 0; nt < 8; ++nt)
#pragma unroll
        for (int j = 0; j < 4; ++j) o[nt][j] = 0.0f;

    const float MASKC = -3.402823466e38f;
    const int row0 = qbase + m0 + gr;
    const int row1 = row0 + 8;

    for (int kb = 0; kb <= qb; ++kb) {
        const int kvbase = kb * 64;
        __syncthreads();
#pragma unroll
        for (int it = 0; it < 4; ++it) {
            int id = tid + it * 128;
            int r = id >> 3, c = id & 7;
            cp16(&sm.K[r][c * 8], &g_kh[gbase + (size_t)(kvbase + r) * HD + c * 8]);
            cp16(&sm.V[r][c * 8], &g_vh[gbase + (size_t)(kvbase + r) * HD + c * 8]);
        }
        CP_COMMIT();
        if (tid < 64) sm.amk[tid] = am[b * SEQ + kvbase + tid];
        CP_WAIT(0);
        __syncthreads();

        // S = Q K^T (m16 x n64, 4 k-steps)
        float s[8][4];
#pragma unroll
        for (int nt = 0; nt < 8; ++nt) {
#pragma unroll
            for (int j = 0; j < 4; ++j) s[nt][j] = 0.0f;
#pragma unroll
            for (int kt = 0; kt < 4; ++kt) {
                uint32_t bk[2];
                bk[0] = ld_u32s(&sm.K[nt * 8 + gr][kt * 16 + 2 * tg]);
                bk[1] = ld_u32s(&sm.K[nt * 8 + gr][kt * 16 + 2 * tg + 8]);
                mma_f16(s[nt], aQ[kt], bk);
            }
        }

        // Mask (faithful) + row max
        float mx0 = -CUDART_INF_F, mx1 = -CUDART_INF_F;
#pragma unroll
        for (int nt = 0; nt < 8; ++nt) {
            const int col = kvbase + nt * 8 + 2 * tg;
            const float ak0 = sm.amk[nt * 8 + 2 * tg];
            const float ak1 = sm.amk[nt * 8 + 2 * tg + 1];
            float mv;
            mv = fmaxf((col     > row0) ? 1.0f : 0.0f, 1.0f - amq0 * ak0);
            s[nt][0] = (s[nt][0] + MASKC * mv) * 0.03125f;
            mv = fmaxf((col + 1 > row0) ? 1.0f : 0.0f, 1.0f - amq0 * ak1);
            s[nt][1] = (s[nt][1] + MASKC * mv) * 0.03125f;
            mv = fmaxf((col     > row1) ? 1.0f : 0.0f, 1.0f - amq1 * ak0);
            s[nt][2] = (s[nt][2] + MASKC * mv) * 0.03125f;
            mv = fmaxf((col + 1 > row1) ? 1.0f : 0.0f, 1.0f - amq1 * ak1);
            s[nt][3] = (s[nt][3] + MASKC * mv) * 0.03125f;
            mx0 = fmaxf(mx0, fmaxf(s[nt][0], s[nt][1]));
            mx1 = fmaxf(mx1, fmaxf(s[nt][2], s[nt][3]));
        }
        mx0 = fmaxf(mx0, __shfl_xor_sync(0xffffffffu, mx0, 1));
        mx0 = fmaxf(mx0, __shfl_xor_sync(0xffffffffu, mx0, 2));
        mx1 = fmaxf(mx1, __shfl_xor_sync(0xffffffffu, mx1, 1));
        mx1 = fmaxf(mx1, __shfl_xor_sync(0xffffffffu, mx1, 2));

        const float mn0 = fmaxf(m0_i, mx0);
        const float mn1 = fmaxf(m1_i, mx1);
        const float f0 = __expf(m0_i - mn0);
        const float f1 = __expf(m1_i - mn1);

        float rs0 = 0.0f, rs1 = 0.0f;
#pragma unroll
        for (int nt = 0; nt < 8; ++nt) {
            float p00 = __expf(s[nt][0] - mn0);
            float p01 = __expf(s[nt][1] - mn0);
            float p10 = __expf(s[nt][2] - mn1);
            float p11 = __expf(s[nt][3] - mn1);
            rs0 += p00 + p01;
            rs1 += p10 + p11;
            *reinterpret_cast<__half2*>(&sm.QP[m0 + gr][nt * 8 + 2 * tg]) =
                __floats2half2_rn(p00, p01);
            *reinterpret_cast<__half2*>(&sm.QP[m0 + gr + 8][nt * 8 + 2 * tg]) =
                __floats2half2_rn(p10, p11);
        }
        rs0 += __shfl_xor_sync(0xffffffffu, rs0, 1);
        rs0 += __shfl_xor_sync(0xffffffffu, rs0, 2);
        rs1 += __shfl_xor_sync(0xffffffffu, rs1, 1);
        rs1 += __shfl_xor_sync(0xffffffffu, rs1, 2);

        l0 = l0 * f0 + rs0;
        l1 = l1 * f1 + rs1;
        m0_i = mn0;
        m1_i = mn1;
#pragma unroll
        for (int nt = 0; nt < 8; ++nt) {
            o[nt][0] *= f0;  o[nt][1] *= f0;
            o[nt][2] *= f1;  o[nt][3] *= f1;
        }
        __syncwarp();

        // O += P V : A-frags from QP (P), B-frags via ldmatrix.x4.trans on V
#pragma unroll
        for (int kt = 0; kt < 4; ++kt) {
            uint32_t aP[4];
            aP[0] = ld_u32s(&sm.QP[m0 + gr][kt * 16 + 2 * tg]);
            aP[1] = ld_u32s(&sm.QP[m0 + gr + 8][kt * 16 + 2 * tg]);
            aP[2] = ld_u32s(&sm.QP[m0 + gr][kt * 16 + 2 * tg + 8]);
            aP[3] = ld_u32s(&sm.QP[m0 + gr + 8][kt * 16 + 2 * tg + 8]);
#pragma unroll
            for (int np = 0; np < 4; ++np) {
                uint32_t addr = vbase +
                    ((uint32_t)(kt * 16 + vlrow) * 72u + (uint32_t)(np * 16) + vlcol) * 2u;
                uint32_t r0, r1, r2, r3;
                ldmatrix_x4_trans(r0, r1, r2, r3, addr);
                uint32_t bv0[2] = {r0, r1};
                uint32_t bv1[2] = {r2, r3};
                mma_f16(o[2 * np],     aP, bv0);
                mma_f16(o[2 * np + 1], aP, bv1);
            }
        }
        __syncwarp();
    }

    // Epilogue: normalize + write half ctx
    const float inv0 = 1.0f / l0;
    const float inv1 = 1.0f / l1;
#pragma unroll
    for (int nt = 0; nt < 8; ++nt) {
        const int cc = nt * 8 + 2 * tg;
        *reinterpret_cast<__half2*>(&g_ch[gbase + (size_t)row0 * HD + cc]) =
            __floats2half2_rn(o[nt][0] * inv0, o[nt][1] * inv0);
        *reinterpret_cast<__half2*>(&g_ch[gbase + (size_t)row1 * HD + cc]) =
            __floats2half2_rn(o[nt][2] * inv1, o[nt][3] * inv1);
    }
}

// ---------------------------------------------------------------------------
extern "C" void kernel_launch(void* const* d_in, const int* in_sizes, int n_in,
                              void* d_out, int out_size)
{
    const float* input = (const float*)d_in[0];
    const float* amask = (const float*)d_in[1];
    const float* wq    = (const float*)d_in[2];
    const float* wk    = (const float*)d_in[3];
    const float* wv    = (const float*)d_in[4];
    const float* wo    = (const float*)d_in[5];
    float* out = (float*)d_out;

    xhalf_kernel<<<ROWS * HD / 4 / 256, 256>>>(input);
    wtrans_kernel<<<dim3(32, 32, 4), dim3(32, 8)>>>(wq, wk, wv, wo);

    dim3 gq(HD / 128, ROWS / 128, 3);     // (8, 32, 3)
    qkv_gemm_kernel<<<gq, 256>>>();

    dim3 gf(SEQ / 64, NHEADS, NB);        // (32, 16, 2)
    flash_tc_kernel<<<gf, 128>>>(amask);

    dim3 go(HD / 128, ROWS / 128);        // (8, 32)
    out_gemm_kernel<<<go, 256>>>(out);
}